// round 9
// baseline (speedup 1.0000x reference)
#include <cuda_runtime.h>

// MFELoss: softmax over C=4, masked squared-error reduction to a scalar.
// HBM-bound streaming reduction: 128 MiB preds (fp32) + 32 MiB target (int32).
// Single kernel: grid-stride reduce + last-block finalize (no 2nd launch tail).

#define NBLK 1216   // 152 SMs x 8 CTAs
#define NTHR 256

// Per-block partials: [0]=fne_sum, [1]=fpe_sum, [2]=fne_count
static __device__ float g_part[NBLK][3];
static __device__ unsigned int g_ticket = 0;   // reset to 0 by last block each launch

__device__ __forceinline__ void accum_row(float4 r, bool is_o, int oi,
                                          float& fne, float& fpe, float& cnt) {
    float m  = fmaxf(fmaxf(r.x, r.y), fmaxf(r.z, r.w));
    float e0 = __expf(r.x - m);
    float e1 = __expf(r.y - m);
    float e2 = __expf(r.z - m);
    float e3 = __expf(r.w - m);
    float inv = __frcp_rn(e0 + e1 + e2 + e3);
    float p0 = e0 * inv, p1 = e1 * inv, p2 = e2 * inv, p3 = e3 * inv;
    float s  = p0 + p1 + p2 + p3;              // numerically ~1, matches reference
    float po = (oi == 0) ? p0 : (oi == 1) ? p1 : (oi == 2) ? p2 : p3;
    float d1 = s - po;
    float d2 = po - 1.0f;
    float fne_i = 0.5f * (d1 * d1 + d2 * d2);
    float fpe_i = po * po;                     // 0.5*((-p)^2 + p^2)
    if (is_o) { fne += fne_i; cnt += 1.0f; }
    else      { fpe += fpe_i; }
}

__global__ void __launch_bounds__(NTHR)
mfe_fused_kernel(const float4* __restrict__ preds,   // [B] rows of 4 floats
                 const int4*   __restrict__ tgt4,    // [B/4] quads of int32
                 const int*    __restrict__ oi_ptr,
                 int n_quads,                        // B/4
                 float n_total,                      // B
                 float* __restrict__ out)
{
    const int oi = *oi_ptr;
    float fne = 0.0f, fpe = 0.0f, cnt = 0.0f;

    const int stride = gridDim.x * blockDim.x;
    for (int i = blockIdx.x * blockDim.x + threadIdx.x; i < n_quads; i += stride) {
        // Front-batch 5 independent streaming loads (no-reuse: bypass-ish L2 policy).
        float4 r0 = __ldcs(&preds[4 * i + 0]);
        float4 r1 = __ldcs(&preds[4 * i + 1]);
        float4 r2 = __ldcs(&preds[4 * i + 2]);
        float4 r3 = __ldcs(&preds[4 * i + 3]);
        int4   t  = __ldcs(&tgt4[i]);
        accum_row(r0, t.x == oi, oi, fne, fpe, cnt);
        accum_row(r1, t.y == oi, oi, fne, fpe, cnt);
        accum_row(r2, t.z == oi, oi, fne, fpe, cnt);
        accum_row(r3, t.w == oi, oi, fne, fpe, cnt);
    }

    // ---- intra-block reduce ----
    #pragma unroll
    for (int off = 16; off > 0; off >>= 1) {
        fne += __shfl_down_sync(0xFFFFFFFFu, fne, off);
        fpe += __shfl_down_sync(0xFFFFFFFFu, fpe, off);
        cnt += __shfl_down_sync(0xFFFFFFFFu, cnt, off);
    }
    __shared__ float s_fne[NTHR / 32];
    __shared__ float s_fpe[NTHR / 32];
    __shared__ float s_cnt[NTHR / 32];
    int lane = threadIdx.x & 31;
    int wid  = threadIdx.x >> 5;
    if (lane == 0) { s_fne[wid] = fne; s_fpe[wid] = fpe; s_cnt[wid] = cnt; }
    __syncthreads();
    if (threadIdx.x < 32) {
        float f = (lane < NTHR / 32) ? s_fne[lane] : 0.0f;
        float p = (lane < NTHR / 32) ? s_fpe[lane] : 0.0f;
        float c = (lane < NTHR / 32) ? s_cnt[lane] : 0.0f;
        #pragma unroll
        for (int off = 4; off > 0; off >>= 1) {
            f += __shfl_down_sync(0xFFFFFFFFu, f, off);
            p += __shfl_down_sync(0xFFFFFFFFu, p, off);
            c += __shfl_down_sync(0xFFFFFFFFu, c, off);
        }
        if (lane == 0) {
            g_part[blockIdx.x][0] = f;
            g_part[blockIdx.x][1] = p;
            g_part[blockIdx.x][2] = c;
        }
    }

    // ---- last-block finalize ----
    __shared__ bool s_is_last;
    __threadfence();                 // g_part writes visible chip-wide
    __syncthreads();
    if (threadIdx.x == 0) {
        unsigned int ticket = atomicAdd(&g_ticket, 1u);
        s_is_last = (ticket == (unsigned int)(gridDim.x - 1));
    }
    __syncthreads();
    if (!s_is_last) return;

    __threadfence();                 // acquire side: see all blocks' partials

    double dfne = 0.0, dfpe = 0.0, dcnt = 0.0;
    for (int i = threadIdx.x; i < NBLK; i += NTHR) {
        dfne += (double)g_part[i][0];
        dfpe += (double)g_part[i][1];
        dcnt += (double)g_part[i][2];
    }
    #pragma unroll
    for (int off = 16; off > 0; off >>= 1) {
        dfne += __shfl_down_sync(0xFFFFFFFFu, dfne, off);
        dfpe += __shfl_down_sync(0xFFFFFFFFu, dfpe, off);
        dcnt += __shfl_down_sync(0xFFFFFFFFu, dcnt, off);
    }
    __shared__ double s_f[NTHR / 32], s_p[NTHR / 32], s_c[NTHR / 32];
    if (lane == 0) { s_f[wid] = dfne; s_p[wid] = dfpe; s_c[wid] = dcnt; }
    __syncthreads();
    if (threadIdx.x == 0) {
        double F = 0.0, P = 0.0, Cn = 0.0;
        #pragma unroll
        for (int w = 0; w < NTHR / 32; w++) { F += s_f[w]; P += s_p[w]; Cn += s_c[w]; }
        float fne_num = (float)Cn;
        float fpe_num = n_total - fne_num;
        out[0] = (float)(P / (double)fpe_num + F / (double)fne_num);
        __threadfence();
        g_ticket = 0;                // deterministic reset for next graph replay
    }
}

extern "C" void kernel_launch(void* const* d_in, const int* in_sizes, int n_in,
                              void* d_out, int out_size)
{
    const float4* preds  = (const float4*)d_in[0];
    const int4*   tgt4   = (const int4*)d_in[1];
    const int*    oi_ptr = (const int*)d_in[2];
    float*        out    = (float*)d_out;

    int n_rows  = in_sizes[0] / 4;     // B
    int n_quads = n_rows / 4;

    mfe_fused_kernel<<<NBLK, NTHR>>>(preds, tgt4, oi_ptr, n_quads, (float)n_rows, out);
}

// round 10
// speedup vs baseline: 1.0314x; 1.0314x over previous
#include <cuda_runtime.h>

// MFELoss: softmax over C=4, masked squared-error reduction to a scalar.
// HBM-bound streaming reduction: 128 MiB preds (fp32) + 32 MiB target (int32).
// Single kernel: grid-stride reduce + last-block finalize. Plain LDG (no .cs —
// it regressed DRAM throughput 5.2 -> 4.2 TB/s in R9).

#define NBLK 1216   // 152 SMs x 8 CTAs
#define NTHR 256

// Per-block partials: [0]=fne_sum, [1]=fpe_sum, [2]=fne_count
static __device__ float g_part[NBLK][3];
static __device__ unsigned int g_ticket = 0;   // reset to 0 by last block each launch

// Simplified per-row math:
//   p_o = exp(r_o) / sum_j exp(r_j) = 1 / sum_j exp(r_j - r_o)
//   s - p_o = (1 - p_o) numerically  =>  fne_i = (1-p_o)^2,  fpe_i = p_o^2
__device__ __forceinline__ void accum_row(float4 r, bool is_o, int oi,
                                          float& fne, float& fpe, float& cnt) {
    float ro = (oi == 0) ? r.x : (oi == 1) ? r.y : (oi == 2) ? r.z : r.w;
    float e0 = __expf(r.x - ro);
    float e1 = __expf(r.y - ro);
    float e2 = __expf(r.z - ro);
    float e3 = __expf(r.w - ro);
    float po = __frcp_rn(e0 + e1 + e2 + e3);
    float d  = 1.0f - po;
    if (is_o) { fne += d * d; cnt += 1.0f; }
    else      { fpe += po * po; }
}

__global__ void __launch_bounds__(NTHR)
mfe_fused_kernel(const float4* __restrict__ preds,   // [B] rows of 4 floats
                 const int4*   __restrict__ tgt4,    // [B/4] quads of int32
                 const int*    __restrict__ oi_ptr,
                 int n_quads,                        // B/4
                 float n_total,                      // B
                 float* __restrict__ out)
{
    const int oi = *oi_ptr;
    float fne = 0.0f, fpe = 0.0f, cnt = 0.0f;

    const int stride = gridDim.x * blockDim.x;
    for (int i = blockIdx.x * blockDim.x + threadIdx.x; i < n_quads; i += stride) {
        // Front-batch 5 independent 16B loads for MLP.
        float4 r0 = preds[4 * i + 0];
        float4 r1 = preds[4 * i + 1];
        float4 r2 = preds[4 * i + 2];
        float4 r3 = preds[4 * i + 3];
        int4   t  = tgt4[i];
        accum_row(r0, t.x == oi, oi, fne, fpe, cnt);
        accum_row(r1, t.y == oi, oi, fne, fpe, cnt);
        accum_row(r2, t.z == oi, oi, fne, fpe, cnt);
        accum_row(r3, t.w == oi, oi, fne, fpe, cnt);
    }

    // ---- intra-block reduce ----
    #pragma unroll
    for (int off = 16; off > 0; off >>= 1) {
        fne += __shfl_down_sync(0xFFFFFFFFu, fne, off);
        fpe += __shfl_down_sync(0xFFFFFFFFu, fpe, off);
        cnt += __shfl_down_sync(0xFFFFFFFFu, cnt, off);
    }
    __shared__ float s_fne[NTHR / 32];
    __shared__ float s_fpe[NTHR / 32];
    __shared__ float s_cnt[NTHR / 32];
    int lane = threadIdx.x & 31;
    int wid  = threadIdx.x >> 5;
    if (lane == 0) { s_fne[wid] = fne; s_fpe[wid] = fpe; s_cnt[wid] = cnt; }
    __syncthreads();
    if (threadIdx.x < 32) {
        float f = (lane < NTHR / 32) ? s_fne[lane] : 0.0f;
        float p = (lane < NTHR / 32) ? s_fpe[lane] : 0.0f;
        float c = (lane < NTHR / 32) ? s_cnt[lane] : 0.0f;
        #pragma unroll
        for (int off = 4; off > 0; off >>= 1) {
            f += __shfl_down_sync(0xFFFFFFFFu, f, off);
            p += __shfl_down_sync(0xFFFFFFFFu, p, off);
            c += __shfl_down_sync(0xFFFFFFFFu, c, off);
        }
        if (lane == 0) {
            g_part[blockIdx.x][0] = f;
            g_part[blockIdx.x][1] = p;
            g_part[blockIdx.x][2] = c;
        }
    }

    // ---- last-block finalize ----
    __shared__ bool s_is_last;
    __threadfence();                 // g_part writes visible chip-wide
    __syncthreads();
    if (threadIdx.x == 0) {
        unsigned int ticket = atomicAdd(&g_ticket, 1u);
        s_is_last = (ticket == (unsigned int)(gridDim.x - 1));
    }
    __syncthreads();
    if (!s_is_last) return;

    __threadfence();                 // acquire side: see all blocks' partials

    double dfne = 0.0, dfpe = 0.0, dcnt = 0.0;
    for (int i = threadIdx.x; i < NBLK; i += NTHR) {
        dfne += (double)g_part[i][0];
        dfpe += (double)g_part[i][1];
        dcnt += (double)g_part[i][2];
    }
    #pragma unroll
    for (int off = 16; off > 0; off >>= 1) {
        dfne += __shfl_down_sync(0xFFFFFFFFu, dfne, off);
        dfpe += __shfl_down_sync(0xFFFFFFFFu, dfpe, off);
        dcnt += __shfl_down_sync(0xFFFFFFFFu, dcnt, off);
    }
    __shared__ double s_f[NTHR / 32], s_p[NTHR / 32], s_c[NTHR / 32];
    if (lane == 0) { s_f[wid] = dfne; s_p[wid] = dfpe; s_c[wid] = dcnt; }
    __syncthreads();
    if (threadIdx.x == 0) {
        double F = 0.0, P = 0.0, Cn = 0.0;
        #pragma unroll
        for (int w = 0; w < NTHR / 32; w++) { F += s_f[w]; P += s_p[w]; Cn += s_c[w]; }
        float fne_num = (float)Cn;
        float fpe_num = n_total - fne_num;
        out[0] = (float)(P / (double)fpe_num + F / (double)fne_num);
        __threadfence();
        g_ticket = 0;                // deterministic reset for next graph replay
    }
}

extern "C" void kernel_launch(void* const* d_in, const int* in_sizes, int n_in,
                              void* d_out, int out_size)
{
    const float4* preds  = (const float4*)d_in[0];
    const int4*   tgt4   = (const int4*)d_in[1];
    const int*    oi_ptr = (const int*)d_in[2];
    float*        out    = (float*)d_out;

    int n_rows  = in_sizes[0] / 4;     // B
    int n_quads = n_rows / 4;

    mfe_fused_kernel<<<NBLK, NTHR>>>(preds, tgt4, oi_ptr, n_quads, (float)n_rows, out);
}

// round 11
// speedup vs baseline: 1.1515x; 1.1164x over previous
#include <cuda_runtime.h>

// MFELoss: softmax over C=4, masked squared-error reduction to a scalar.
// HBM-bound streaming reduction: 128 MiB preds (fp32) + 32 MiB target (int32).
// Single fused kernel sized to EXACTLY one wave: 36 regs -> 7 CTAs/SM on 152 SMs.
// (R10 ran 1216 blocks at 7 CTAs/SM occupancy -> 152-block straggler wave, ~+5us.)

#define NBLK 1064   // 152 SMs x 7 CTAs  == one full wave at 36 regs
#define NTHR 256

// Per-block partials: [0]=fne_sum, [1]=fpe_sum, [2]=fne_count
static __device__ float g_part[NBLK][3];
static __device__ unsigned int g_ticket = 0;   // reset to 0 by last block each launch

// Simplified per-row math:
//   p_o = 1 / sum_j exp(r_j - r_o);   fne_i = (1-p_o)^2,  fpe_i = p_o^2
__device__ __forceinline__ void accum_row(float4 r, bool is_o, int oi,
                                          float& fne, float& fpe, float& cnt) {
    float ro = (oi == 0) ? r.x : (oi == 1) ? r.y : (oi == 2) ? r.z : r.w;
    float e0 = __expf(r.x - ro);
    float e1 = __expf(r.y - ro);
    float e2 = __expf(r.z - ro);
    float e3 = __expf(r.w - ro);
    float po = __frcp_rn(e0 + e1 + e2 + e3);
    float d  = 1.0f - po;
    if (is_o) { fne += d * d; cnt += 1.0f; }
    else      { fpe += po * po; }
}

__global__ void __launch_bounds__(NTHR, 7)
mfe_fused_kernel(const float4* __restrict__ preds,   // [B] rows of 4 floats
                 const int4*   __restrict__ tgt4,    // [B/4] quads of int32
                 const int*    __restrict__ oi_ptr,
                 int n_quads,                        // B/4
                 float n_total,                      // B
                 float* __restrict__ out)
{
    const int oi = *oi_ptr;
    float fne = 0.0f, fpe = 0.0f, cnt = 0.0f;

    const int stride = gridDim.x * blockDim.x;
    for (int i = blockIdx.x * blockDim.x + threadIdx.x; i < n_quads; i += stride) {
        // Front-batch 5 independent 16B loads for MLP.
        float4 r0 = preds[4 * i + 0];
        float4 r1 = preds[4 * i + 1];
        float4 r2 = preds[4 * i + 2];
        float4 r3 = preds[4 * i + 3];
        int4   t  = tgt4[i];
        accum_row(r0, t.x == oi, oi, fne, fpe, cnt);
        accum_row(r1, t.y == oi, oi, fne, fpe, cnt);
        accum_row(r2, t.z == oi, oi, fne, fpe, cnt);
        accum_row(r3, t.w == oi, oi, fne, fpe, cnt);
    }

    // ---- intra-block reduce ----
    #pragma unroll
    for (int off = 16; off > 0; off >>= 1) {
        fne += __shfl_down_sync(0xFFFFFFFFu, fne, off);
        fpe += __shfl_down_sync(0xFFFFFFFFu, fpe, off);
        cnt += __shfl_down_sync(0xFFFFFFFFu, cnt, off);
    }
    __shared__ float s_fne[NTHR / 32];
    __shared__ float s_fpe[NTHR / 32];
    __shared__ float s_cnt[NTHR / 32];
    int lane = threadIdx.x & 31;
    int wid  = threadIdx.x >> 5;
    if (lane == 0) { s_fne[wid] = fne; s_fpe[wid] = fpe; s_cnt[wid] = cnt; }
    __syncthreads();
    if (threadIdx.x < 32) {
        float f = (lane < NTHR / 32) ? s_fne[lane] : 0.0f;
        float p = (lane < NTHR / 32) ? s_fpe[lane] : 0.0f;
        float c = (lane < NTHR / 32) ? s_cnt[lane] : 0.0f;
        #pragma unroll
        for (int off = 4; off > 0; off >>= 1) {
            f += __shfl_down_sync(0xFFFFFFFFu, f, off);
            p += __shfl_down_sync(0xFFFFFFFFu, p, off);
            c += __shfl_down_sync(0xFFFFFFFFu, c, off);
        }
        if (lane == 0) {
            g_part[blockIdx.x][0] = f;
            g_part[blockIdx.x][1] = p;
            g_part[blockIdx.x][2] = c;
        }
    }

    // ---- last-block finalize ----
    __shared__ bool s_is_last;
    __threadfence();                 // release: g_part writes visible chip-wide
    __syncthreads();
    if (threadIdx.x == 0) {
        unsigned int ticket = atomicAdd(&g_ticket, 1u);
        s_is_last = (ticket == (unsigned int)(gridDim.x - 1));
    }
    __syncthreads();
    if (!s_is_last) return;

    __threadfence();                 // acquire: see all blocks' partials

    double dfne = 0.0, dfpe = 0.0, dcnt = 0.0;
    for (int i = threadIdx.x; i < NBLK; i += NTHR) {
        dfne += (double)g_part[i][0];
        dfpe += (double)g_part[i][1];
        dcnt += (double)g_part[i][2];
    }
    #pragma unroll
    for (int off = 16; off > 0; off >>= 1) {
        dfne += __shfl_down_sync(0xFFFFFFFFu, dfne, off);
        dfpe += __shfl_down_sync(0xFFFFFFFFu, dfpe, off);
        dcnt += __shfl_down_sync(0xFFFFFFFFu, dcnt, off);
    }
    __shared__ double s_f[NTHR / 32], s_p[NTHR / 32], s_c[NTHR / 32];
    if (lane == 0) { s_f[wid] = dfne; s_p[wid] = dfpe; s_c[wid] = dcnt; }
    __syncthreads();
    if (threadIdx.x == 0) {
        double F = 0.0, P = 0.0, Cn = 0.0;
        #pragma unroll
        for (int w = 0; w < NTHR / 32; w++) { F += s_f[w]; P += s_p[w]; Cn += s_c[w]; }
        float fne_num = (float)Cn;
        float fpe_num = n_total - fne_num;
        out[0] = (float)(P / (double)fpe_num + F / (double)fne_num);
        __threadfence();
        g_ticket = 0;                // deterministic reset for next graph replay
    }
}

extern "C" void kernel_launch(void* const* d_in, const int* in_sizes, int n_in,
                              void* d_out, int out_size)
{
    const float4* preds  = (const float4*)d_in[0];
    const int4*   tgt4   = (const int4*)d_in[1];
    const int*    oi_ptr = (const int*)d_in[2];
    float*        out    = (float*)d_out;

    int n_rows  = in_sizes[0] / 4;     // B
    int n_quads = n_rows / 4;

    mfe_fused_kernel<<<NBLK, NTHR>>>(preds, tgt4, oi_ptr, n_quads, (float)n_rows, out);
}